// round 16
// baseline (speedup 1.0000x reference)
#include <cuda_runtime.h>
#include <cstddef>
#include <cstdint>

#define EPS 1e-8f
#define DELTA2 2.0e-4f          // 2*delta safety margin for filter guarantee

static constexpr int B    = 1024;
static constexpr int K    = 512;
static constexpr int E    = 64;
static constexpr int D    = 769;
static constexpr int TOPK = 64;
static constexpr int SURV = 128;   // survivors per row (approx-top-128)

typedef unsigned long long u64;

__device__ float g_aw[B * E];
__device__ float g_la[B * E];
__device__ float g_ascore[B * K];   // approximate confusion scores
__device__ int   g_idx[B * TOPK];
__device__ int   g_flag[B];         // 1 -> fallback row

// ---------------------------------------------------------------------------
// Packed f32x2 helpers (R14 form — measured best). add2 = two exact rn adds.
// ---------------------------------------------------------------------------
__device__ __forceinline__ u64 pk2(float lo, float hi) {
    u64 r; asm("mov.b64 %0, {%1, %2};" : "=l"(r) : "f"(lo), "f"(hi)); return r;
}
__device__ __forceinline__ void upk2(u64 v, float& lo, float& hi) {
    asm("mov.b64 {%0, %1}, %2;" : "=f"(lo), "=f"(hi) : "l"(v));
}
__device__ __forceinline__ u64 add2(u64 a, u64 b) {
    u64 r; asm("add.rn.f32x2 %0, %1, %2;" : "=l"(r) : "l"(a), "l"(b)); return r;
}

// ---------------------------------------------------------------------------
// Scalar XLA-CPU log (Eigen plog / Cephes, no FMA) — proven bit-exact vs the
// reference. DO NOT MODIFY.
// ---------------------------------------------------------------------------
__device__ __forceinline__ float xla_logf(float xin) {
    float x = fmaxf(xin, __uint_as_float(0x00800000u));
    uint32_t bits = __float_as_uint(x);
    int emm0 = (int)(bits >> 23) - 126;
    float e = (float)emm0;
    float m = __uint_as_float((bits & 0x807fffffu) | 0x3f000000u);
    bool mask = m < __uint_as_float(0x3f3504f3u);
    float tmp = mask ? m : 0.0f;
    float xx = __fadd_rn(__fsub_rn(m, 1.0f), tmp);
    e = __fsub_rn(e, mask ? 1.0f : 0.0f);

    float z = __fmul_rn(xx, xx);
    float y = 7.0376836292e-2f;
    y = __fadd_rn(__fmul_rn(y, xx), -1.1514610310e-1f);
    y = __fadd_rn(__fmul_rn(y, xx),  1.1676998740e-1f);
    y = __fadd_rn(__fmul_rn(y, xx), -1.2420140846e-1f);
    y = __fadd_rn(__fmul_rn(y, xx),  1.4249322787e-1f);
    y = __fadd_rn(__fmul_rn(y, xx), -1.6668057665e-1f);
    y = __fadd_rn(__fmul_rn(y, xx),  2.0000714765e-1f);
    y = __fadd_rn(__fmul_rn(y, xx), -2.4999993993e-1f);
    y = __fadd_rn(__fmul_rn(y, xx),  3.3333331174e-1f);
    y = __fmul_rn(y, xx);
    y = __fmul_rn(y, z);
    y = __fadd_rn(y, __fmul_rn(e, -2.12194440e-4f));
    y = __fsub_rn(y, __fmul_rn(z, 0.5f));
    float r = __fadd_rn(xx, y);
    r = __fadd_rn(r, __fmul_rn(e, 0.693359375f));
    return r;
}

// ---------------------------------------------------------------------------
// Fast approximate ln for the filter: ln(x) = e*ln2 + 2*atanh(s),
// s = (m-1)/(m+1) in [0,1/3], Taylor through s^7.
// |fast_ln - xla_logf| <= ~2.5e-5 << delta = 1e-4 for x in [1e-8, 1.3].
// ---------------------------------------------------------------------------
__device__ __forceinline__ float fast_ln(float x) {
    uint32_t bits = __float_as_uint(x);
    int e = (int)(bits >> 23) - 127;
    float m = __uint_as_float((bits & 0x007fffffu) | 0x3f800000u);  // [1,2)
    float rmp;
    asm("rcp.approx.f32 %0, %1;" : "=f"(rmp) : "f"(m + 1.0f));
    float s  = (m - 1.0f) * rmp;
    float s2 = s * s;
    float p = fmaf(s2, 0.28571429f, 0.4f);      // 2/7, 2/5
    p = fmaf(s2, p, 0.66666669f);               // 2/3
    p = fmaf(s2, p, 2.0f);
    return fmaf((float)e, 0.69314718f, s * p);
}

#define NEON_HORIZ(a0, a1, a2, a3) __fadd_rn(__fadd_rn(a0, a2), __fadd_rn(a1, a3))

// ---------------------------------------------------------------------------
// Exact per-candidate score — the PROVEN R5/R7 scalar path (two-pass global
// read, NEON 4-acc reduce, div.rn, xla_logf). Bit-exact vs reference.
// ---------------------------------------------------------------------------
__device__ __forceinline__ float exact_score(
    const float* __restrict__ neg, int b, int idx,
    const float* s_a, const float* s_la)
{
    const float4* row = (const float4*)(neg + ((size_t)b * K + idx) * E);
    float a0 = 0.f, a1 = 0.f, a2 = 0.f, a3 = 0.f;
    #pragma unroll
    for (int c = 0; c < 16; c++) {
        float4 v;
        asm volatile("ld.global.nc.v4.f32 {%0,%1,%2,%3}, [%4];"
                     : "=f"(v.x), "=f"(v.y), "=f"(v.z), "=f"(v.w)
                     : "l"(row + c));
        a0 = __fadd_rn(a0, __fadd_rn(v.x, EPS));
        a1 = __fadd_rn(a1, __fadd_rn(v.y, EPS));
        a2 = __fadd_rn(a2, __fadd_rn(v.z, EPS));
        a3 = __fadd_rn(a3, __fadd_rn(v.w, EPS));
    }
    float S = NEON_HORIZ(a0, a1, a2, a3);

    float k0 = 0.f, k1 = 0.f, k2 = 0.f, k3 = 0.f;
    #pragma unroll 4
    for (int c = 0; c < 16; c++) {
        float4 v = __ldg(row + c);
        int e = 4 * c;
        float nn0 = __fdiv_rn(__fadd_rn(v.x, EPS), S);
        float nn1 = __fdiv_rn(__fadd_rn(v.y, EPS), S);
        float nn2 = __fdiv_rn(__fadd_rn(v.z, EPS), S);
        float nn3 = __fdiv_rn(__fadd_rn(v.w, EPS), S);
        float ln0 = xla_logf(__fadd_rn(nn0, EPS));
        float ln1 = xla_logf(__fadd_rn(nn1, EPS));
        float ln2 = xla_logf(__fadd_rn(nn2, EPS));
        float ln3 = xla_logf(__fadd_rn(nn3, EPS));
        k0 = __fadd_rn(k0, __fmul_rn(s_a[e+0], __fsub_rn(s_la[e+0], ln0)));
        k1 = __fadd_rn(k1, __fmul_rn(s_a[e+1], __fsub_rn(s_la[e+1], ln1)));
        k2 = __fadd_rn(k2, __fmul_rn(s_a[e+2], __fsub_rn(s_la[e+2], ln2)));
        k3 = __fadd_rn(k3, __fmul_rn(s_a[e+3], __fsub_rn(s_la[e+3], ln3)));
    }
    return -NEON_HORIZ(k0, k1, k2, k3);
}

// ---------------------------------------------------------------------------
// K1: anchor rows (scalar, proven, unchanged).
// ---------------------------------------------------------------------------
__global__ __launch_bounds__(256) void k_anchor(const float* __restrict__ anchor) {
    int b = blockIdx.x * blockDim.x + threadIdx.x;
    if (b >= B) return;
    const float4* row = (const float4*)(anchor + b * E);
    float4 vv[16];
    float a0 = 0.f, a1 = 0.f, a2 = 0.f, a3 = 0.f;
    #pragma unroll
    for (int c = 0; c < 16; c++) {
        vv[c] = __ldg(row + c);
        a0 = __fadd_rn(a0, __fadd_rn(vv[c].x, EPS));
        a1 = __fadd_rn(a1, __fadd_rn(vv[c].y, EPS));
        a2 = __fadd_rn(a2, __fadd_rn(vv[c].z, EPS));
        a3 = __fadd_rn(a3, __fadd_rn(vv[c].w, EPS));
    }
    float S = NEON_HORIZ(a0, a1, a2, a3);
    const float* vf = (const float*)vv;
    #pragma unroll
    for (int e = 0; e < E; e++) {
        float a = __fdiv_rn(__fadd_rn(vf[e], EPS), S);
        g_aw[b * E + e] = a;
        g_la[b * E + e] = xla_logf(__fadd_rn(a, EPS));
    }
}

// ---------------------------------------------------------------------------
// K2: APPROX filter scores — R14 memory structure (coalesced tile load +
// transpose into padded smem), exact S, fast_ln scoring.
// ---------------------------------------------------------------------------
__global__ __launch_bounds__(128, 6) void k_scores_approx(const float* __restrict__ neg) {
    __shared__ float s_a[E], s_la[E];
    __shared__ u64 srow[32][129];    // [chunk][candidate], elem (2q, 2q+1)

    int b   = blockIdx.x >> 2;
    int k0  = (blockIdx.x & 3) << 7;
    int tid = threadIdx.x;
    if (tid < E) {
        s_a[tid]  = __ldg(&g_aw[b * E + tid]);
        s_la[tid] = __ldg(&g_la[b * E + tid]);
    }

    const u64 EPS2 = pk2(EPS, EPS);

    // coalesced load + transpose (adds EPS, packed)
    const float4* tile = (const float4*)(neg + ((size_t)b * K + k0) * E);
    #pragma unroll
    for (int i = 0; i < 16; i++) {
        int f = tid + (i << 7);
        int r  = f >> 4;
        int c2 = f & 15;
        float4 v = __ldg(tile + f);
        u64 lo, hi;
        asm("mov.b64 %0, {%1, %2};" : "=l"(lo) : "f"(v.x), "f"(v.y));
        asm("mov.b64 %0, {%1, %2};" : "=l"(hi) : "f"(v.z), "f"(v.w));
        srow[2 * c2][r]     = add2(lo, EPS2);
        srow[2 * c2 + 1][r] = add2(hi, EPS2);
    }
    __syncthreads();

    // exact row sum (packed rn adds, NEON order — bitwise == exact path S)
    u64 acc01 = 0ull, acc23 = 0ull;
    #pragma unroll
    for (int c = 0; c < 16; c++) {
        acc01 = add2(acc01, srow[2 * c][tid]);
        acc23 = add2(acc23, srow[2 * c + 1][tid]);
    }
    float h02, h13;
    upk2(add2(acc01, acc23), h02, h13);
    float S = __fadd_rn(h02, h13);
    float yr;
    asm("rcp.approx.f32 %0, %1;" : "=f"(yr) : "f"(S));

    // approximate KL accumulation
    float acc0 = 0.f, acc1 = 0.f;
    #pragma unroll 8
    for (int q = 0; q < 32; q++) {
        float f0, f1;
        upk2(srow[q][tid], f0, f1);
        int e0 = 2 * q, e1 = 2 * q + 1;
        float ln0 = fast_ln(fmaf(f0, yr, EPS));
        float ln1 = fast_ln(fmaf(f1, yr, EPS));
        acc0 = fmaf(s_a[e0], s_la[e0] - ln0, acc0);
        acc1 = fmaf(s_a[e1], s_la[e1] - ln1, acc1);
    }
    g_ascore[b * K + k0 + tid] = -(acc0 + acc1);
}

// ---------------------------------------------------------------------------
// K3: select + exact rescore. Per row: bitonic-sort 512 approx scores,
// verify the filter guarantee gap, exact-rescore the top-128 survivors with
// the proven path, bitonic-sort 128, emit top-64.
// ---------------------------------------------------------------------------
__global__ __launch_bounds__(512) void k_select(
    const float* __restrict__ neg, float* __restrict__ out_scores)
{
    __shared__ float ss[K];
    __shared__ int   si[K];
    __shared__ float s_a[E], s_la[E];

    int b = blockIdx.x, tid = threadIdx.x;
    if (tid < E) {
        s_a[tid]  = g_aw[b * E + tid];
        s_la[tid] = g_la[b * E + tid];
    }
    ss[tid] = g_ascore[b * K + tid];
    si[tid] = tid;

    // bitonic sort 512 (desc, ties -> lower index) — proven code
    for (int sz = 2; sz <= K; sz <<= 1) {
        for (int j = sz >> 1; j > 0; j >>= 1) {
            __syncthreads();
            int ixj = tid ^ j;
            if (ixj > tid) {
                bool desc = ((tid & sz) == 0);
                float s1 = ss[tid], s2 = ss[ixj];
                int   i1 = si[tid], i2 = si[ixj];
                bool g = (s1 > s2) || (s1 == s2 && i1 < i2);
                if (g != desc) {
                    ss[tid] = s2; ss[ixj] = s1;
                    si[tid] = i2; si[ixj] = i1;
                }
            }
        }
    }
    __syncthreads();

    // filter-soundness gap check: a128 < a64 - 2*delta
    bool flag = !(ss[SURV - 1] < ss[TOPK - 1] - DELTA2);
    if (tid == 0) g_flag[b] = flag ? 1 : 0;
    if (flag) return;                       // uniform branch; fallback covers

    // exact rescore of survivors (threads 0..127, proven scalar path)
    float es = 0.f; int eidx = 0;
    if (tid < SURV) {
        eidx = si[tid];
        es = exact_score(neg, b, eidx, s_a, s_la);
    }
    __syncthreads();
    if (tid < SURV) { ss[tid] = es; si[tid] = eidx; }
    __syncthreads();

    // bitonic sort 128 (desc, ties -> lower index)
    for (int sz = 2; sz <= SURV; sz <<= 1) {
        for (int j = sz >> 1; j > 0; j >>= 1) {
            __syncthreads();
            if (tid < SURV) {
                int ixj = tid ^ j;
                if (ixj > tid) {
                    bool desc = ((tid & sz) == 0);
                    float s1 = ss[tid], s2 = ss[ixj];
                    int   i1 = si[tid], i2 = si[ixj];
                    bool g = (s1 > s2) || (s1 == s2 && i1 < i2);
                    if (g != desc) {
                        ss[tid] = s2; ss[ixj] = s1;
                        si[tid] = i2; si[ixj] = i1;
                    }
                }
            }
        }
    }
    __syncthreads();
    if (tid < TOPK) {
        out_scores[b * TOPK + tid] = ss[tid];
        g_idx[b * TOPK + tid]      = si[tid];
    }
}

// ---------------------------------------------------------------------------
// K4: fallback — full exact scores + sort for flagged rows (rarely runs).
// ---------------------------------------------------------------------------
__global__ __launch_bounds__(512) void k_fallback(
    const float* __restrict__ neg, float* __restrict__ out_scores)
{
    int b = blockIdx.x, tid = threadIdx.x;
    if (g_flag[b] == 0) return;             // uniform early exit

    __shared__ float ss[K];
    __shared__ int   si[K];
    __shared__ float s_a[E], s_la[E];
    if (tid < E) {
        s_a[tid]  = g_aw[b * E + tid];
        s_la[tid] = g_la[b * E + tid];
    }
    __syncthreads();

    ss[tid] = exact_score(neg, b, tid, s_a, s_la);
    si[tid] = tid;

    for (int sz = 2; sz <= K; sz <<= 1) {
        for (int j = sz >> 1; j > 0; j >>= 1) {
            __syncthreads();
            int ixj = tid ^ j;
            if (ixj > tid) {
                bool desc = ((tid & sz) == 0);
                float s1 = ss[tid], s2 = ss[ixj];
                int   i1 = si[tid], i2 = si[ixj];
                bool g = (s1 > s2) || (s1 == s2 && i1 < i2);
                if (g != desc) {
                    ss[tid] = s2; ss[ixj] = s1;
                    si[tid] = i2; si[ixj] = i1;
                }
            }
        }
    }
    __syncthreads();
    if (tid < TOPK) {
        out_scores[b * TOPK + tid] = ss[tid];
        g_idx[b * TOPK + tid]      = si[tid];
    }
}

// ---------------------------------------------------------------------------
// K5: gather (scalar, proven best — at scattered-row DRAM floor).
// ---------------------------------------------------------------------------
__global__ __launch_bounds__(128) void k_gather(
    const float* __restrict__ cand, float* __restrict__ out_hard)
{
    int blk = blockIdx.x;
    int b = blk >> 6, j = blk & (TOPK - 1);
    int idx = g_idx[b * TOPK + j];
    const float* __restrict__ src = cand + ((size_t)b * K + idx) * D;
    float* __restrict__ dst = out_hard + ((size_t)b * TOPK + j) * D;
    #pragma unroll
    for (int i = threadIdx.x; i < D; i += 128)
        dst[i] = __ldg(src + i);
}

// ---------------------------------------------------------------------------
extern "C" void kernel_launch(void* const* d_in, const int* in_sizes, int n_in,
                              void* d_out, int out_size) {
    const float* anchor = (const float*)d_in[0];  // (B, E)
    const float* neg    = (const float*)d_in[1];  // (B, K, E)
    const float* cand   = (const float*)d_in[2];  // (B, K, D)
    float* out        = (float*)d_out;
    float* out_hard   = out;                          // (B, TOPK, D)
    float* out_scores = out + (size_t)B * TOPK * D;   // (B, TOPK)

    k_anchor<<<4, 256>>>(anchor);
    k_scores_approx<<<B * 4, 128>>>(neg);
    k_select<<<B, 512>>>(neg, out_scores);
    k_fallback<<<B, 512>>>(neg, out_scores);
    k_gather<<<B * TOPK, 128>>>(cand, out_hard);
}

// round 17
// speedup vs baseline: 1.0846x; 1.0846x over previous
#include <cuda_runtime.h>
#include <cstddef>
#include <cstdint>

#define EPS 1e-8f
#define DELTA2 2.0e-4f          // 2*delta safety margin for filter guarantee

static constexpr int B    = 1024;
static constexpr int K    = 512;
static constexpr int E    = 64;
static constexpr int D    = 769;
static constexpr int TOPK = 64;
static constexpr int SURV = 128;   // survivors per row (approx-top-128)

typedef unsigned long long u64;

__device__ float g_aw[B * E];
__device__ float g_la[B * E];
__device__ float g_ascore[B * K];   // approximate confusion scores
__device__ int   g_idx[B * TOPK];
__device__ int   g_flag[B];         // 1 -> fallback row

// ---------------------------------------------------------------------------
__device__ __forceinline__ u64 pk2(float lo, float hi) {
    u64 r; asm("mov.b64 %0, {%1, %2};" : "=l"(r) : "f"(lo), "f"(hi)); return r;
}
__device__ __forceinline__ void upk2(u64 v, float& lo, float& hi) {
    asm("mov.b64 {%0, %1}, %2;" : "=f"(lo), "=f"(hi) : "l"(v));
}
__device__ __forceinline__ u64 add2(u64 a, u64 b) {
    u64 r; asm("add.rn.f32x2 %0, %1, %2;" : "=l"(r) : "l"(a), "l"(b)); return r;
}

// ---------------------------------------------------------------------------
// Scalar XLA-CPU log (Eigen plog / Cephes, no FMA) — proven bit-exact vs the
// reference. DO NOT MODIFY.
// ---------------------------------------------------------------------------
__device__ __forceinline__ float xla_logf(float xin) {
    float x = fmaxf(xin, __uint_as_float(0x00800000u));
    uint32_t bits = __float_as_uint(x);
    int emm0 = (int)(bits >> 23) - 126;
    float e = (float)emm0;
    float m = __uint_as_float((bits & 0x807fffffu) | 0x3f000000u);
    bool mask = m < __uint_as_float(0x3f3504f3u);
    float tmp = mask ? m : 0.0f;
    float xx = __fadd_rn(__fsub_rn(m, 1.0f), tmp);
    e = __fsub_rn(e, mask ? 1.0f : 0.0f);

    float z = __fmul_rn(xx, xx);
    float y = 7.0376836292e-2f;
    y = __fadd_rn(__fmul_rn(y, xx), -1.1514610310e-1f);
    y = __fadd_rn(__fmul_rn(y, xx),  1.1676998740e-1f);
    y = __fadd_rn(__fmul_rn(y, xx), -1.2420140846e-1f);
    y = __fadd_rn(__fmul_rn(y, xx),  1.4249322787e-1f);
    y = __fadd_rn(__fmul_rn(y, xx), -1.6668057665e-1f);
    y = __fadd_rn(__fmul_rn(y, xx),  2.0000714765e-1f);
    y = __fadd_rn(__fmul_rn(y, xx), -2.4999993993e-1f);
    y = __fadd_rn(__fmul_rn(y, xx),  3.3333331174e-1f);
    y = __fmul_rn(y, xx);
    y = __fmul_rn(y, z);
    y = __fadd_rn(y, __fmul_rn(e, -2.12194440e-4f));
    y = __fsub_rn(y, __fmul_rn(z, 0.5f));
    float r = __fadd_rn(xx, y);
    r = __fadd_rn(r, __fmul_rn(e, 0.693359375f));
    return r;
}

// ---------------------------------------------------------------------------
// Fast approximate ln for the filter (R16, proven sound with delta=1e-4).
// ---------------------------------------------------------------------------
__device__ __forceinline__ float fast_ln(float x) {
    uint32_t bits = __float_as_uint(x);
    int e = (int)(bits >> 23) - 127;
    float m = __uint_as_float((bits & 0x007fffffu) | 0x3f800000u);  // [1,2)
    float rmp;
    asm("rcp.approx.f32 %0, %1;" : "=f"(rmp) : "f"(m + 1.0f));
    float s  = (m - 1.0f) * rmp;
    float s2 = s * s;
    float p = fmaf(s2, 0.28571429f, 0.4f);
    p = fmaf(s2, p, 0.66666669f);
    p = fmaf(s2, p, 2.0f);
    return fmaf((float)e, 0.69314718f, s * p);
}

#define NEON_HORIZ(a0, a1, a2, a3) __fadd_rn(__fadd_rn(a0, a2), __fadd_rn(a1, a3))

// ---------------------------------------------------------------------------
// Exact per-candidate score (proven R5/R7 path) — used by fallback only.
// ---------------------------------------------------------------------------
__device__ __forceinline__ float exact_score(
    const float* __restrict__ neg, int b, int idx,
    const float* s_a, const float* s_la)
{
    const float4* row = (const float4*)(neg + ((size_t)b * K + idx) * E);
    float a0 = 0.f, a1 = 0.f, a2 = 0.f, a3 = 0.f;
    #pragma unroll
    for (int c = 0; c < 16; c++) {
        float4 v;
        asm volatile("ld.global.nc.v4.f32 {%0,%1,%2,%3}, [%4];"
                     : "=f"(v.x), "=f"(v.y), "=f"(v.z), "=f"(v.w)
                     : "l"(row + c));
        a0 = __fadd_rn(a0, __fadd_rn(v.x, EPS));
        a1 = __fadd_rn(a1, __fadd_rn(v.y, EPS));
        a2 = __fadd_rn(a2, __fadd_rn(v.z, EPS));
        a3 = __fadd_rn(a3, __fadd_rn(v.w, EPS));
    }
    float S = NEON_HORIZ(a0, a1, a2, a3);

    float k0 = 0.f, k1 = 0.f, k2 = 0.f, k3 = 0.f;
    #pragma unroll 4
    for (int c = 0; c < 16; c++) {
        float4 v = __ldg(row + c);
        int e = 4 * c;
        float nn0 = __fdiv_rn(__fadd_rn(v.x, EPS), S);
        float nn1 = __fdiv_rn(__fadd_rn(v.y, EPS), S);
        float nn2 = __fdiv_rn(__fadd_rn(v.z, EPS), S);
        float nn3 = __fdiv_rn(__fadd_rn(v.w, EPS), S);
        float ln0 = xla_logf(__fadd_rn(nn0, EPS));
        float ln1 = xla_logf(__fadd_rn(nn1, EPS));
        float ln2 = xla_logf(__fadd_rn(nn2, EPS));
        float ln3 = xla_logf(__fadd_rn(nn3, EPS));
        k0 = __fadd_rn(k0, __fmul_rn(s_a[e+0], __fsub_rn(s_la[e+0], ln0)));
        k1 = __fadd_rn(k1, __fmul_rn(s_a[e+1], __fsub_rn(s_la[e+1], ln1)));
        k2 = __fadd_rn(k2, __fmul_rn(s_a[e+2], __fsub_rn(s_la[e+2], ln2)));
        k3 = __fadd_rn(k3, __fmul_rn(s_a[e+3], __fsub_rn(s_la[e+3], ln3)));
    }
    return -NEON_HORIZ(k0, k1, k2, k3);
}

// ---------------------------------------------------------------------------
// K1: anchor rows (scalar, proven, unchanged).
// ---------------------------------------------------------------------------
__global__ __launch_bounds__(256) void k_anchor(const float* __restrict__ anchor) {
    int b = blockIdx.x * blockDim.x + threadIdx.x;
    if (b >= B) return;
    const float4* row = (const float4*)(anchor + b * E);
    float4 vv[16];
    float a0 = 0.f, a1 = 0.f, a2 = 0.f, a3 = 0.f;
    #pragma unroll
    for (int c = 0; c < 16; c++) {
        vv[c] = __ldg(row + c);
        a0 = __fadd_rn(a0, __fadd_rn(vv[c].x, EPS));
        a1 = __fadd_rn(a1, __fadd_rn(vv[c].y, EPS));
        a2 = __fadd_rn(a2, __fadd_rn(vv[c].z, EPS));
        a3 = __fadd_rn(a3, __fadd_rn(vv[c].w, EPS));
    }
    float S = NEON_HORIZ(a0, a1, a2, a3);
    const float* vf = (const float*)vv;
    #pragma unroll
    for (int e = 0; e < E; e++) {
        float a = __fdiv_rn(__fadd_rn(vf[e], EPS), S);
        g_aw[b * E + e] = a;
        g_la[b * E + e] = xla_logf(__fadd_rn(a, EPS));
    }
}

// ---------------------------------------------------------------------------
// K2: APPROX filter scores (R16, unchanged — coalesced transpose + fast_ln).
// ---------------------------------------------------------------------------
__global__ __launch_bounds__(128, 6) void k_scores_approx(const float* __restrict__ neg) {
    __shared__ float s_a[E], s_la[E];
    __shared__ u64 srow[32][129];

    int b   = blockIdx.x >> 2;
    int k0  = (blockIdx.x & 3) << 7;
    int tid = threadIdx.x;
    if (tid < E) {
        s_a[tid]  = __ldg(&g_aw[b * E + tid]);
        s_la[tid] = __ldg(&g_la[b * E + tid]);
    }

    const u64 EPS2 = pk2(EPS, EPS);
    const float4* tile = (const float4*)(neg + ((size_t)b * K + k0) * E);
    #pragma unroll
    for (int i = 0; i < 16; i++) {
        int f = tid + (i << 7);
        int r  = f >> 4;
        int c2 = f & 15;
        float4 v = __ldg(tile + f);
        u64 lo, hi;
        asm("mov.b64 %0, {%1, %2};" : "=l"(lo) : "f"(v.x), "f"(v.y));
        asm("mov.b64 %0, {%1, %2};" : "=l"(hi) : "f"(v.z), "f"(v.w));
        srow[2 * c2][r]     = add2(lo, EPS2);
        srow[2 * c2 + 1][r] = add2(hi, EPS2);
    }
    __syncthreads();

    u64 acc01 = 0ull, acc23 = 0ull;
    #pragma unroll
    for (int c = 0; c < 16; c++) {
        acc01 = add2(acc01, srow[2 * c][tid]);
        acc23 = add2(acc23, srow[2 * c + 1][tid]);
    }
    float h02, h13;
    upk2(add2(acc01, acc23), h02, h13);
    float S = __fadd_rn(h02, h13);
    float yr;
    asm("rcp.approx.f32 %0, %1;" : "=f"(yr) : "f"(S));

    float acc0 = 0.f, acc1 = 0.f;
    #pragma unroll 8
    for (int q = 0; q < 32; q++) {
        float f0, f1;
        upk2(srow[q][tid], f0, f1);
        int e0 = 2 * q, e1 = 2 * q + 1;
        float ln0 = fast_ln(fmaf(f0, yr, EPS));
        float ln1 = fast_ln(fmaf(f1, yr, EPS));
        acc0 = fmaf(s_a[e0], s_la[e0] - ln0, acc0);
        acc1 = fmaf(s_a[e1], s_la[e1] - ln1, acc1);
    }
    g_ascore[b * K + k0 + tid] = -(acc0 + acc1);
}

// ---------------------------------------------------------------------------
// K3: select + exact rescore. Sort 512 approx; gap check; COALESCED staged
// load of 128 survivor rows into transposed smem; exact rescore with 4
// threads/survivor (one NEON accumulator each — bit-identical combine via
// shfl); sort 128; emit top-64.
// ---------------------------------------------------------------------------
__global__ __launch_bounds__(512) void k_select(
    const float* __restrict__ neg, float* __restrict__ out_scores)
{
    __shared__ float ss[K];
    __shared__ int   si[K];
    __shared__ float s_a[E], s_la[E];
    __shared__ u64 srow[32][129];    // [chunk][survivor] staging

    int b = blockIdx.x, tid = threadIdx.x;
    if (tid < E) {
        s_a[tid]  = g_aw[b * E + tid];
        s_la[tid] = g_la[b * E + tid];
    }
    ss[tid] = g_ascore[b * K + tid];
    si[tid] = tid;

    // bitonic sort 512 (desc, ties -> lower index) — proven code
    for (int sz = 2; sz <= K; sz <<= 1) {
        for (int j = sz >> 1; j > 0; j >>= 1) {
            __syncthreads();
            int ixj = tid ^ j;
            if (ixj > tid) {
                bool desc = ((tid & sz) == 0);
                float s1 = ss[tid], s2 = ss[ixj];
                int   i1 = si[tid], i2 = si[ixj];
                bool g = (s1 > s2) || (s1 == s2 && i1 < i2);
                if (g != desc) {
                    ss[tid] = s2; ss[ixj] = s1;
                    si[tid] = i2; si[ixj] = i1;
                }
            }
        }
    }
    __syncthreads();

    // filter-soundness gap check (proven in R16)
    bool flag = !(ss[SURV - 1] < ss[TOPK - 1] - DELTA2);
    if (tid == 0) g_flag[b] = flag ? 1 : 0;
    if (flag) return;

    // ---- coalesced staged load of 128 survivor rows (adds EPS, packed) ---
    const u64 EPS2 = pk2(EPS, EPS);
    const float* nb = neg + (size_t)b * K * E;
    #pragma unroll
    for (int i = 0; i < 4; i++) {
        int f = tid + (i << 9);          // 0..2047
        int s = f >> 4;                  // survivor slot 0..127
        int q = f & 15;                  // float4 slot in row
        const float4* src = (const float4*)(nb + (size_t)si[s] * E) + q;
        float4 v = __ldg(src);
        u64 lo, hi;
        asm("mov.b64 %0, {%1, %2};" : "=l"(lo) : "f"(v.x), "f"(v.y));
        asm("mov.b64 %0, {%1, %2};" : "=l"(hi) : "f"(v.z), "f"(v.w));
        srow[2 * q][s]     = add2(lo, EPS2);
        srow[2 * q + 1][s] = add2(hi, EPS2);
    }
    __syncthreads();

    // ---- exact rescore: 4 threads per survivor (NEON accumulator jj) -----
    int s  = tid >> 2;
    int jj = tid & 3;
    int ch_half = jj >> 1, half = jj & 1;

    // pass 1: acc_jj = sequential sum of ne[4c+jj], c = 0..15
    float acc = 0.f;
    #pragma unroll
    for (int c = 0; c < 16; c++) {
        float lo, hi;
        upk2(srow[2 * c + ch_half][s], lo, hi);
        acc = __fadd_rn(acc, half ? hi : lo);
    }
    // S = (a0+a2)+(a1+a3): xor-2 then xor-1 — commutative, bit-identical
    float t2 = __fadd_rn(acc, __shfl_xor_sync(0xffffffffu, acc, 2));
    float S  = __fadd_rn(t2,  __shfl_xor_sync(0xffffffffu, t2, 1));

    // pass 2: k_jj = sequential sum of a*(la-ln) over e = 4c+jj
    float kacc = 0.f;
    #pragma unroll 4
    for (int c = 0; c < 16; c++) {
        float lo, hi;
        upk2(srow[2 * c + ch_half][s], lo, hi);
        float ne = half ? hi : lo;
        int e = 4 * c + jj;
        float nn = __fdiv_rn(ne, S);
        float ln = xla_logf(__fadd_rn(nn, EPS));
        kacc = __fadd_rn(kacc, __fmul_rn(s_a[e], __fsub_rn(s_la[e], ln)));
    }
    float u2 = __fadd_rn(kacc, __shfl_xor_sync(0xffffffffu, kacc, 2));
    float kl = __fadd_rn(u2,  __shfl_xor_sync(0xffffffffu, u2, 1));

    __syncthreads();
    if (jj == 0) ss[s] = -kl;            // si[s] keeps original index
    __syncthreads();

    // ---- bitonic sort 128 (desc, ties -> lower index) ---------------------
    for (int sz = 2; sz <= SURV; sz <<= 1) {
        for (int j = sz >> 1; j > 0; j >>= 1) {
            __syncthreads();
            if (tid < SURV) {
                int ixj = tid ^ j;
                if (ixj > tid) {
                    bool desc = ((tid & sz) == 0);
                    float s1 = ss[tid], s2 = ss[ixj];
                    int   i1 = si[tid], i2 = si[ixj];
                    bool g = (s1 > s2) || (s1 == s2 && i1 < i2);
                    if (g != desc) {
                        ss[tid] = s2; ss[ixj] = s1;
                        si[tid] = i2; si[ixj] = i1;
                    }
                }
            }
        }
    }
    __syncthreads();
    if (tid < TOPK) {
        out_scores[b * TOPK + tid] = ss[tid];
        g_idx[b * TOPK + tid]      = si[tid];
    }
}

// ---------------------------------------------------------------------------
// K4: fallback — full exact scores + sort for flagged rows (proven; idle).
// ---------------------------------------------------------------------------
__global__ __launch_bounds__(512) void k_fallback(
    const float* __restrict__ neg, float* __restrict__ out_scores)
{
    int b = blockIdx.x, tid = threadIdx.x;
    if (g_flag[b] == 0) return;

    __shared__ float ss[K];
    __shared__ int   si[K];
    __shared__ float s_a[E], s_la[E];
    if (tid < E) {
        s_a[tid]  = g_aw[b * E + tid];
        s_la[tid] = g_la[b * E + tid];
    }
    __syncthreads();

    ss[tid] = exact_score(neg, b, tid, s_a, s_la);
    si[tid] = tid;

    for (int sz = 2; sz <= K; sz <<= 1) {
        for (int j = sz >> 1; j > 0; j >>= 1) {
            __syncthreads();
            int ixj = tid ^ j;
            if (ixj > tid) {
                bool desc = ((tid & sz) == 0);
                float s1 = ss[tid], s2 = ss[ixj];
                int   i1 = si[tid], i2 = si[ixj];
                bool g = (s1 > s2) || (s1 == s2 && i1 < i2);
                if (g != desc) {
                    ss[tid] = s2; ss[ixj] = s1;
                    si[tid] = i2; si[ixj] = i1;
                }
            }
        }
    }
    __syncthreads();
    if (tid < TOPK) {
        out_scores[b * TOPK + tid] = ss[tid];
        g_idx[b * TOPK + tid]      = si[tid];
    }
}

// ---------------------------------------------------------------------------
// K5: gather (scalar, proven best — at scattered-row DRAM floor).
// ---------------------------------------------------------------------------
__global__ __launch_bounds__(128) void k_gather(
    const float* __restrict__ cand, float* __restrict__ out_hard)
{
    int blk = blockIdx.x;
    int b = blk >> 6, j = blk & (TOPK - 1);
    int idx = g_idx[b * TOPK + j];
    const float* __restrict__ src = cand + ((size_t)b * K + idx) * D;
    float* __restrict__ dst = out_hard + ((size_t)b * TOPK + j) * D;
    #pragma unroll
    for (int i = threadIdx.x; i < D; i += 128)
        dst[i] = __ldg(src + i);
}

// ---------------------------------------------------------------------------
extern "C" void kernel_launch(void* const* d_in, const int* in_sizes, int n_in,
                              void* d_out, int out_size) {
    const float* anchor = (const float*)d_in[0];  // (B, E)
    const float* neg    = (const float*)d_in[1];  // (B, K, E)
    const float* cand   = (const float*)d_in[2];  // (B, K, D)
    float* out        = (float*)d_out;
    float* out_hard   = out;                          // (B, TOPK, D)
    float* out_scores = out + (size_t)B * TOPK * D;   // (B, TOPK)

    k_anchor<<<4, 256>>>(anchor);
    k_scores_approx<<<B * 4, 128>>>(neg);
    k_select<<<B, 512>>>(neg, out_scores);
    k_fallback<<<B, 512>>>(neg, out_scores);
    k_gather<<<B * TOPK, 128>>>(cand, out_hard);
}